// round 1
// baseline (speedup 1.0000x reference)
#include <cuda_runtime.h>
#include <cstddef>

#define B_ 4
#define L_ 512
#define HID_ 512
#define H_ 8
#define DH_ 64

// ---------------- scratch (device globals; no allocations allowed) ----------
__device__ float g_q[B_ * L_ * HID_];
__device__ float g_k[B_ * L_ * HID_];
__device__ float g_v[B_ * L_ * HID_];
__device__ float g_sc[B_ * H_ * L_ * L_];   // scores, then probs (in place)

// ---------------- packed f32x2 FMA ------------------------------------------
__device__ __forceinline__ void ffma2(float2& d, const float2 a, const float2 b) {
    asm("fma.rn.f32x2 %0, %1, %2, %0;"
        : "+l"(reinterpret_cast<unsigned long long&>(d))
        : "l"(reinterpret_cast<const unsigned long long&>(a)),
          "l"(reinterpret_cast<const unsigned long long&>(b)));
}
__device__ __forceinline__ float2 fdup(float a) { return make_float2(a, a); }

// =============================================================================
// K1: QKV projection.  C[m][n] = sum_k X[m][k] * W[n][k] + bias[n]
// X: (2048, 512) row-major.  W: (512, 512) row-major (row = out feature).
// BM=BN=128, BK=16, 256 threads, 8x8 micro-tile (f32x2 paired over rows).
// =============================================================================
__global__ __launch_bounds__(256) void k_proj(
    const float* __restrict__ X,
    const float* __restrict__ Wq, const float* __restrict__ bq,
    const float* __restrict__ Wk, const float* __restrict__ bk,
    const float* __restrict__ Wv, const float* __restrict__ bv)
{
    __shared__ float As[16][132];
    __shared__ float Bs[16][132];

    const float* W; const float* bias; float* C;
    if (blockIdx.z == 0)      { W = Wq; bias = bq; C = g_q; }
    else if (blockIdx.z == 1) { W = Wk; bias = bk; C = g_k; }
    else                      { W = Wv; bias = bv; C = g_v; }

    const int m0 = blockIdx.y * 128;
    const int n0 = blockIdx.x * 128;
    const int tid = threadIdx.x;
    const int tx = tid & 15, ty = tid >> 4;
    const int lrow = tid >> 2;   // 0..63
    const int lf   = tid & 3;    // k-float4 index

    float2 acc[4][8];
#pragma unroll
    for (int i = 0; i < 4; i++)
#pragma unroll
        for (int j = 0; j < 8; j++) acc[i][j] = make_float2(0.f, 0.f);

    for (int k0 = 0; k0 < 512; k0 += 16) {
#pragma unroll
        for (int r = 0; r < 2; r++) {
            int row = lrow + r * 64;
            float4 a4 = *(const float4*)&X[(size_t)(m0 + row) * 512 + k0 + lf * 4];
            As[lf * 4 + 0][row] = a4.x; As[lf * 4 + 1][row] = a4.y;
            As[lf * 4 + 2][row] = a4.z; As[lf * 4 + 3][row] = a4.w;
            float4 b4 = *(const float4*)&W[(size_t)(n0 + row) * 512 + k0 + lf * 4];
            Bs[lf * 4 + 0][row] = b4.x; Bs[lf * 4 + 1][row] = b4.y;
            Bs[lf * 4 + 2][row] = b4.z; Bs[lf * 4 + 3][row] = b4.w;
        }
        __syncthreads();
#pragma unroll
        for (int kk = 0; kk < 16; kk++) {
            float4 a0 = *(const float4*)&As[kk][ty * 8];
            float4 a1 = *(const float4*)&As[kk][ty * 8 + 4];
            float4 b0 = *(const float4*)&Bs[kk][tx * 8];
            float4 b1 = *(const float4*)&Bs[kk][tx * 8 + 4];
            float2 a2[4] = { make_float2(a0.x, a0.y), make_float2(a0.z, a0.w),
                             make_float2(a1.x, a1.y), make_float2(a1.z, a1.w) };
            float bj[8] = { b0.x, b0.y, b0.z, b0.w, b1.x, b1.y, b1.z, b1.w };
#pragma unroll
            for (int j = 0; j < 8; j++) {
                float2 bd = fdup(bj[j]);
#pragma unroll
                for (int i = 0; i < 4; i++) ffma2(acc[i][j], a2[i], bd);
            }
        }
        __syncthreads();
    }

    float bvv[8];
#pragma unroll
    for (int j = 0; j < 8; j++) bvv[j] = bias[n0 + tx * 8 + j];

#pragma unroll
    for (int i = 0; i < 4; i++) {
        int m = m0 + ty * 8 + 2 * i;
        float4* p0 = (float4*)&C[(size_t)m * 512 + n0 + tx * 8];
        p0[0] = make_float4(acc[i][0].x + bvv[0], acc[i][1].x + bvv[1],
                            acc[i][2].x + bvv[2], acc[i][3].x + bvv[3]);
        p0[1] = make_float4(acc[i][4].x + bvv[4], acc[i][5].x + bvv[5],
                            acc[i][6].x + bvv[6], acc[i][7].x + bvv[7]);
        float4* p1 = (float4*)&C[(size_t)(m + 1) * 512 + n0 + tx * 8];
        p1[0] = make_float4(acc[i][0].y + bvv[0], acc[i][1].y + bvv[1],
                            acc[i][2].y + bvv[2], acc[i][3].y + bvv[3]);
        p1[1] = make_float4(acc[i][4].y + bvv[4], acc[i][5].y + bvv[5],
                            acc[i][6].y + bvv[6], acc[i][7].y + bvv[7]);
    }
}

// =============================================================================
// K2: scores = q . k^T  per (b,h).  S[qi][ki] = sum_d q[..d] * k[..d]
// M=N=512, K=64.  BM=BN=128, BK=16, same micro as K1.
// =============================================================================
__global__ __launch_bounds__(256) void k_scores()
{
    __shared__ float As[16][132];
    __shared__ float Bs[16][132];

    const int bh = blockIdx.z;             // 0..31
    const int b = bh >> 3, h = bh & 7;
    const int m0 = blockIdx.y * 128;       // q tile
    const int n0 = blockIdx.x * 128;       // k tile
    const float* A  = g_q + (size_t)b * L_ * HID_ + h * DH_;
    const float* Bm = g_k + (size_t)b * L_ * HID_ + h * DH_;
    float* C = g_sc + (size_t)bh * L_ * L_;

    const int tid = threadIdx.x;
    const int tx = tid & 15, ty = tid >> 4;
    const int lrow = tid >> 2;
    const int lf   = tid & 3;

    float2 acc[4][8];
#pragma unroll
    for (int i = 0; i < 4; i++)
#pragma unroll
        for (int j = 0; j < 8; j++) acc[i][j] = make_float2(0.f, 0.f);

    for (int k0 = 0; k0 < 64; k0 += 16) {
#pragma unroll
        for (int r = 0; r < 2; r++) {
            int row = lrow + r * 64;
            float4 a4 = *(const float4*)&A[(size_t)(m0 + row) * 512 + k0 + lf * 4];
            As[lf * 4 + 0][row] = a4.x; As[lf * 4 + 1][row] = a4.y;
            As[lf * 4 + 2][row] = a4.z; As[lf * 4 + 3][row] = a4.w;
            float4 b4 = *(const float4*)&Bm[(size_t)(n0 + row) * 512 + k0 + lf * 4];
            Bs[lf * 4 + 0][row] = b4.x; Bs[lf * 4 + 1][row] = b4.y;
            Bs[lf * 4 + 2][row] = b4.z; Bs[lf * 4 + 3][row] = b4.w;
        }
        __syncthreads();
#pragma unroll
        for (int kk = 0; kk < 16; kk++) {
            float4 a0 = *(const float4*)&As[kk][ty * 8];
            float4 a1 = *(const float4*)&As[kk][ty * 8 + 4];
            float4 b0 = *(const float4*)&Bs[kk][tx * 8];
            float4 b1 = *(const float4*)&Bs[kk][tx * 8 + 4];
            float2 a2[4] = { make_float2(a0.x, a0.y), make_float2(a0.z, a0.w),
                             make_float2(a1.x, a1.y), make_float2(a1.z, a1.w) };
            float bj[8] = { b0.x, b0.y, b0.z, b0.w, b1.x, b1.y, b1.z, b1.w };
#pragma unroll
            for (int j = 0; j < 8; j++) {
                float2 bd = fdup(bj[j]);
#pragma unroll
                for (int i = 0; i < 4; i++) ffma2(acc[i][j], a2[i], bd);
            }
        }
        __syncthreads();
    }

#pragma unroll
    for (int i = 0; i < 4; i++) {
        int m = m0 + ty * 8 + 2 * i;
        float4* p0 = (float4*)&C[(size_t)m * 512 + n0 + tx * 8];
        p0[0] = make_float4(acc[i][0].x, acc[i][1].x, acc[i][2].x, acc[i][3].x);
        p0[1] = make_float4(acc[i][4].x, acc[i][5].x, acc[i][6].x, acc[i][7].x);
        float4* p1 = (float4*)&C[(size_t)(m + 1) * 512 + n0 + tx * 8];
        p1[0] = make_float4(acc[i][0].y, acc[i][1].y, acc[i][2].y, acc[i][3].y);
        p1[1] = make_float4(acc[i][4].y, acc[i][5].y, acc[i][6].y, acc[i][7].y);
    }
}

// =============================================================================
// K3: fused per-(b,q):  rels in smem once -> rel scores + combine + softmax
//     + probs*rels.  Writes probs back to g_sc and rel-ctx to d_out.
// smem: r_s[512][68], sc_s[8][512], q_s[64][8] (reused as reduce buffer)
// =============================================================================
#define SMEM_FUSED ((512 * 68 + 8 * 512 + 512) * 4)

__global__ __launch_bounds__(256) void k_fused(
    const float* __restrict__ rels,
    const float* __restrict__ heads,
    float* __restrict__ out)
{
    extern __shared__ float sm[];
    float* r_s  = sm;                   // 512*68
    float* sc_s = sm + 512 * 68;        // 8*512
    float* q_s  = sc_s + 8 * 512;       // 512

    const int bq = blockIdx.x;
    const int b = bq >> 9, q = bq & 511;
    const int tid = threadIdx.x;
    const int lane = tid & 31, w = tid >> 5;

    // ---- load rels[b,q] -> smem (pitch 68) ----
    const float* rg = rels + (size_t)bq * (512 * 64);
#pragma unroll 4
    for (int it = 0; it < 32; it++) {
        int idx = it * 256 + tid;        // float4 index, 0..8191
        int row = idx >> 4, c4 = idx & 15;
        float4 v = *(const float4*)&rg[row * 64 + c4 * 4];
        *(float4*)&r_s[row * 68 + c4 * 4] = v;
    }
    // ---- load q vector transposed: q_s[d*8 + h] ----
    if (tid < 128) {
        const float* qg = g_q + ((size_t)b * L_ + q) * HID_;
        float4 v = *(const float4*)&qg[tid * 4];
        int e = tid * 4;
        q_s[((e + 0) & 63) * 8 + ((e + 0) >> 6)] = v.x;
        q_s[((e + 1) & 63) * 8 + ((e + 1) >> 6)] = v.y;
        q_s[((e + 2) & 63) * 8 + ((e + 2) >> 6)] = v.z;
        q_s[((e + 3) & 63) * 8 + ((e + 3) >> 6)] = v.w;
    }
    __syncthreads();

    // ---- stage B: rel scores for k0 = w*64+lane, k1 = k0+32 ----
    const int k0 = w * 64 + lane, k1 = k0 + 32;
    float2 acc0[4], acc1[4];
#pragma unroll
    for (int i = 0; i < 4; i++) { acc0[i] = make_float2(0.f, 0.f); acc1[i] = make_float2(0.f, 0.f); }

#pragma unroll
    for (int d = 0; d < 64; d += 4) {
        float4 ra = *(const float4*)&r_s[k0 * 68 + d];
        float4 rb = *(const float4*)&r_s[k1 * 68 + d];
        float raj[4] = { ra.x, ra.y, ra.z, ra.w };
        float rbj[4] = { rb.x, rb.y, rb.z, rb.w };
#pragma unroll
        for (int j = 0; j < 4; j++) {
            float4 qA = *(const float4*)&q_s[(d + j) * 8];
            float4 qB = *(const float4*)&q_s[(d + j) * 8 + 4];
            float2 rad = fdup(raj[j]);
            float2 rbd = fdup(rbj[j]);
            ffma2(acc0[0], rad, make_float2(qA.x, qA.y));
            ffma2(acc0[1], rad, make_float2(qA.z, qA.w));
            ffma2(acc0[2], rad, make_float2(qB.x, qB.y));
            ffma2(acc0[3], rad, make_float2(qB.z, qB.w));
            ffma2(acc1[0], rbd, make_float2(qA.x, qA.y));
            ffma2(acc1[1], rbd, make_float2(qA.z, qA.w));
            ffma2(acc1[2], rbd, make_float2(qB.x, qB.y));
            ffma2(acc1[3], rbd, make_float2(qB.z, qB.w));
        }
    }

    // ---- combine with qk scores, scale, add mask ----
    {
        float hv0 = heads[((size_t)b * 512 + q) * 512 + k0];
        float hv1 = heads[((size_t)b * 512 + q) * 512 + k1];
#pragma unroll
        for (int hp = 0; hp < 4; hp++) {
            int h0 = 2 * hp, h1 = 2 * hp + 1;
            const float* s0 = g_sc + (((size_t)(b * 8 + h0)) * 512 + q) * 512;
            const float* s1 = g_sc + (((size_t)(b * 8 + h1)) * 512 + q) * 512;
            sc_s[h0 * 512 + k0] = (acc0[hp].x + s0[k0]) * 0.125f + hv0;
            sc_s[h0 * 512 + k1] = (acc1[hp].x + s0[k1]) * 0.125f + hv1;
            sc_s[h1 * 512 + k0] = (acc0[hp].y + s1[k0]) * 0.125f + hv0;
            sc_s[h1 * 512 + k1] = (acc1[hp].y + s1[k1]) * 0.125f + hv1;
        }
    }
    __syncthreads();

    // ---- stage C: softmax, warp w == head w ----
    {
        float* row = sc_s + w * 512;
        float vals[16];
        float mx = -1e30f;
#pragma unroll
        for (int i = 0; i < 16; i++) { vals[i] = row[i * 32 + lane]; mx = fmaxf(mx, vals[i]); }
#pragma unroll
        for (int o = 16; o; o >>= 1) mx = fmaxf(mx, __shfl_xor_sync(0xffffffffu, mx, o));
        float s = 0.f;
#pragma unroll
        for (int i = 0; i < 16; i++) { vals[i] = __expf(vals[i] - mx); s += vals[i]; }
#pragma unroll
        for (int o = 16; o; o >>= 1) s += __shfl_xor_sync(0xffffffffu, s, o);
        float inv = 1.f / s;
        float* pg = g_sc + (((size_t)(b * 8 + w)) * 512 + q) * 512;
#pragma unroll
        for (int i = 0; i < 16; i++) {
            float p = vals[i] * inv;
            row[i * 32 + lane] = p;
            pg[i * 32 + lane] = p;
        }
    }
    __syncthreads();

    // ---- stage D: rel-ctx = probs . rels (k-split by 2) ----
    {
        const int ks = tid >> 7;        // 0/1: which half of k
        const int r  = tid & 127;
        const int h  = r >> 4;          // 0..7
        const int dq = r & 15;          // 0..15
        const int d0 = dq * 4;
        float2 c0 = make_float2(0.f, 0.f), c1 = make_float2(0.f, 0.f);
        const float* prow = sc_s + h * 512;
        const int kbeg = ks * 256;
#pragma unroll 8
        for (int k = kbeg; k < kbeg + 256; k += 4) {
            float4 p4 = *(const float4*)&prow[k];
            float pj[4] = { p4.x, p4.y, p4.z, p4.w };
#pragma unroll
            for (int j = 0; j < 4; j++) {
                float4 r4 = *(const float4*)&r_s[(k + j) * 68 + d0];
                float2 pd = fdup(pj[j]);
                ffma2(c0, pd, make_float2(r4.x, r4.y));
                ffma2(c1, pd, make_float2(r4.z, r4.w));
            }
        }
        if (ks == 1) {
            *(float4*)&q_s[r * 4] = make_float4(c0.x, c0.y, c1.x, c1.y);
        }
        __syncthreads();
        if (ks == 0) {
            float4 t = *(const float4*)&q_s[r * 4];
            float4 o = make_float4(c0.x + t.x, c0.y + t.y, c1.x + t.z, c1.y + t.w);
            *(float4*)&out[(size_t)bq * 512 + h * 64 + d0] = o;
        }
    }
}

// =============================================================================
// K4: ctx += probs @ v  per (b,h).  M=512(q), N=64(d), K=512(k).
// BM=128, BN=64, BK=16, 256 threads, micro 8x4.  out += (rel-ctx already there)
// =============================================================================
__global__ __launch_bounds__(256) void k_ctx(float* __restrict__ out)
{
    __shared__ float As[16][132];   // probs^T: [kk][m]
    __shared__ float Bs[16][68];    // v: [kk][n]

    const int bh = blockIdx.y;
    const int b = bh >> 3, h = bh & 7;
    const int m0 = blockIdx.x * 128;
    const float* P = g_sc + (size_t)bh * L_ * L_;
    const float* V = g_v + (size_t)b * L_ * HID_ + h * DH_;

    const int tid = threadIdx.x;
    const int tx = tid & 15, ty = tid >> 4;
    const int lrow = tid >> 2;
    const int lf   = tid & 3;
    const int vrow = tid >> 4;       // 0..15
    const int vc   = tid & 15;       // 0..15

    float2 acc[4][4];
#pragma unroll
    for (int i = 0; i < 4; i++)
#pragma unroll
        for (int j = 0; j < 4; j++) acc[i][j] = make_float2(0.f, 0.f);

    for (int k0 = 0; k0 < 512; k0 += 16) {
#pragma unroll
        for (int r = 0; r < 2; r++) {
            int row = lrow + r * 64;
            float4 a4 = *(const float4*)&P[(size_t)(m0 + row) * 512 + k0 + lf * 4];
            As[lf * 4 + 0][row] = a4.x; As[lf * 4 + 1][row] = a4.y;
            As[lf * 4 + 2][row] = a4.z; As[lf * 4 + 3][row] = a4.w;
        }
        {
            float4 b4 = *(const float4*)&V[(size_t)(k0 + vrow) * 512 + vc * 4];
            *(float4*)&Bs[vrow][vc * 4] = b4;
        }
        __syncthreads();
#pragma unroll
        for (int kk = 0; kk < 16; kk++) {
            float4 a0 = *(const float4*)&As[kk][ty * 8];
            float4 a1 = *(const float4*)&As[kk][ty * 8 + 4];
            float4 b4 = *(const float4*)&Bs[kk][tx * 4];
            float2 a2[4] = { make_float2(a0.x, a0.y), make_float2(a0.z, a0.w),
                             make_float2(a1.x, a1.y), make_float2(a1.z, a1.w) };
            float bj[4] = { b4.x, b4.y, b4.z, b4.w };
#pragma unroll
            for (int j = 0; j < 4; j++) {
                float2 bd = fdup(bj[j]);
#pragma unroll
                for (int i = 0; i < 4; i++) ffma2(acc[i][j], a2[i], bd);
            }
        }
        __syncthreads();
    }

#pragma unroll
    for (int i = 0; i < 4; i++) {
        int m = m0 + ty * 8 + 2 * i;
        float4* p0 = (float4*)&out[((size_t)b * 512 + m) * 512 + h * 64 + tx * 4];
        float4 c0 = *p0;
        c0.x += acc[i][0].x; c0.y += acc[i][1].x; c0.z += acc[i][2].x; c0.w += acc[i][3].x;
        *p0 = c0;
        float4* p1 = (float4*)&out[((size_t)b * 512 + m + 1) * 512 + h * 64 + tx * 4];
        float4 c1 = *p1;
        c1.x += acc[i][0].y; c1.y += acc[i][1].y; c1.z += acc[i][2].y; c1.w += acc[i][3].y;
        *p1 = c1;
    }
}

// =============================================================================
extern "C" void kernel_launch(void* const* d_in, const int* in_sizes, int n_in,
                              void* d_out, int out_size)
{
    const float* hidden = (const float*)d_in[0];
    const float* heads  = (const float*)d_in[1];
    const float* rels   = (const float*)d_in[2];
    const float* Wq = (const float*)d_in[3];
    const float* bq = (const float*)d_in[4];
    const float* Wk = (const float*)d_in[5];
    const float* bk = (const float*)d_in[6];
    const float* Wv = (const float*)d_in[7];
    const float* bv = (const float*)d_in[8];
    float* out = (float*)d_out;

    dim3 g1(4, 16, 3);     // N/128, M/128 (2048/128), {q,k,v}
    k_proj<<<g1, 256>>>(hidden, Wq, bq, Wk, bk, Wv, bv);

    dim3 g2(4, 4, 32);     // k-tiles, q-tiles, b*h
    k_scores<<<g2, 256>>>();

    cudaFuncSetAttribute(k_fused, cudaFuncAttributeMaxDynamicSharedMemorySize, SMEM_FUSED);
    k_fused<<<2048, 256, SMEM_FUSED>>>(rels, heads, out);

    dim3 g4(4, 32);        // q-tiles, b*h
    k_ctx<<<g4, 256>>>(out);
}

// round 2
// speedup vs baseline: 1.0429x; 1.0429x over previous
#include <cuda_runtime.h>
#include <cstddef>

#define B_ 4
#define L_ 512
#define HID_ 512
#define H_ 8
#define DH_ 64

// ---------------- scratch (device globals; no allocations allowed) ----------
__device__ float g_q[B_ * L_ * HID_];
__device__ float g_k[B_ * L_ * HID_];
__device__ float g_v[B_ * L_ * HID_];
__device__ float g_sc[B_ * H_ * L_ * L_];   // scores, then probs (in place)

// ---------------- packed f32x2 FMA ------------------------------------------
__device__ __forceinline__ void ffma2(float2& d, const float2 a, const float2 b) {
    asm("fma.rn.f32x2 %0, %1, %2, %0;"
        : "+l"(reinterpret_cast<unsigned long long&>(d))
        : "l"(reinterpret_cast<const unsigned long long&>(a)),
          "l"(reinterpret_cast<const unsigned long long&>(b)));
}
__device__ __forceinline__ float2 fdup(float a) { return make_float2(a, a); }

// ---------------- cp.async helpers ------------------------------------------
__device__ __forceinline__ void cp_async16(void* smem, const void* gmem) {
    unsigned s = (unsigned)__cvta_generic_to_shared(smem);
    asm volatile("cp.async.cg.shared.global [%0], [%1], 16;\n" :: "r"(s), "l"(gmem));
}
__device__ __forceinline__ void cp_commit() {
    asm volatile("cp.async.commit_group;\n");
}
template <int N>
__device__ __forceinline__ void cp_wait() {
    asm volatile("cp.async.wait_group %0;\n" :: "n"(N));
}

// =============================================================================
// K1: QKV projection.  C[m][n] = sum_k X[m][k] * W[n][k] + bias[n]
// BM=128, BN=64, BK=16, 256 threads, micro 8x4 (f32x2 over row pairs).
// grid (8, 16, 3) = 384 CTAs.
// =============================================================================
__global__ __launch_bounds__(256) void k_proj(
    const float* __restrict__ X,
    const float* __restrict__ Wq, const float* __restrict__ bq,
    const float* __restrict__ Wk, const float* __restrict__ bk,
    const float* __restrict__ Wv, const float* __restrict__ bv)
{
    __shared__ float As[16][132];
    __shared__ float Bs[16][68];

    const float* W; const float* bias; float* C;
    if (blockIdx.z == 0)      { W = Wq; bias = bq; C = g_q; }
    else if (blockIdx.z == 1) { W = Wk; bias = bk; C = g_k; }
    else                      { W = Wv; bias = bv; C = g_v; }

    const int m0 = blockIdx.y * 128;
    const int n0 = blockIdx.x * 64;
    const int tid = threadIdx.x;
    const int tx = tid & 15, ty = tid >> 4;   // cols tx*4, rows ty*8
    const int lrow = tid >> 2;                // 0..63
    const int lf   = tid & 3;

    float2 acc[4][4];
#pragma unroll
    for (int i = 0; i < 4; i++)
#pragma unroll
        for (int j = 0; j < 4; j++) acc[i][j] = make_float2(0.f, 0.f);

    for (int k0 = 0; k0 < 512; k0 += 16) {
#pragma unroll
        for (int r = 0; r < 2; r++) {
            int row = lrow + r * 64;
            float4 a4 = *(const float4*)&X[(size_t)(m0 + row) * 512 + k0 + lf * 4];
            As[lf * 4 + 0][row] = a4.x; As[lf * 4 + 1][row] = a4.y;
            As[lf * 4 + 2][row] = a4.z; As[lf * 4 + 3][row] = a4.w;
        }
        {
            float4 b4 = *(const float4*)&W[(size_t)(n0 + lrow) * 512 + k0 + lf * 4];
            Bs[lf * 4 + 0][lrow] = b4.x; Bs[lf * 4 + 1][lrow] = b4.y;
            Bs[lf * 4 + 2][lrow] = b4.z; Bs[lf * 4 + 3][lrow] = b4.w;
        }
        __syncthreads();
#pragma unroll
        for (int kk = 0; kk < 16; kk++) {
            float4 a0 = *(const float4*)&As[kk][ty * 8];
            float4 a1 = *(const float4*)&As[kk][ty * 8 + 4];
            float4 b4 = *(const float4*)&Bs[kk][tx * 4];
            float2 a2[4] = { make_float2(a0.x, a0.y), make_float2(a0.z, a0.w),
                             make_float2(a1.x, a1.y), make_float2(a1.z, a1.w) };
            float bj[4] = { b4.x, b4.y, b4.z, b4.w };
#pragma unroll
            for (int j = 0; j < 4; j++) {
                float2 bd = fdup(bj[j]);
#pragma unroll
                for (int i = 0; i < 4; i++) ffma2(acc[i][j], a2[i], bd);
            }
        }
        __syncthreads();
    }

    float bvv[4];
#pragma unroll
    for (int j = 0; j < 4; j++) bvv[j] = bias[n0 + tx * 4 + j];

#pragma unroll
    for (int i = 0; i < 4; i++) {
        int m = m0 + ty * 8 + 2 * i;
        *(float4*)&C[(size_t)m * 512 + n0 + tx * 4] =
            make_float4(acc[i][0].x + bvv[0], acc[i][1].x + bvv[1],
                        acc[i][2].x + bvv[2], acc[i][3].x + bvv[3]);
        *(float4*)&C[(size_t)(m + 1) * 512 + n0 + tx * 4] =
            make_float4(acc[i][0].y + bvv[0], acc[i][1].y + bvv[1],
                        acc[i][2].y + bvv[2], acc[i][3].y + bvv[3]);
    }
}

// =============================================================================
// K2: scores = q . k^T per (b,h).  BM=128(q), BN=64(k), K=64.
// grid (8, 4, 32) = 1024 CTAs.
// =============================================================================
__global__ __launch_bounds__(256) void k_scores()
{
    __shared__ float As[16][132];
    __shared__ float Bs[16][68];

    const int bh = blockIdx.z;
    const int b = bh >> 3, h = bh & 7;
    const int m0 = blockIdx.y * 128;
    const int n0 = blockIdx.x * 64;
    const float* A  = g_q + (size_t)b * L_ * HID_ + h * DH_;
    const float* Bm = g_k + (size_t)b * L_ * HID_ + h * DH_;
    float* C = g_sc + (size_t)bh * L_ * L_;

    const int tid = threadIdx.x;
    const int tx = tid & 15, ty = tid >> 4;
    const int lrow = tid >> 2;
    const int lf   = tid & 3;

    float2 acc[4][4];
#pragma unroll
    for (int i = 0; i < 4; i++)
#pragma unroll
        for (int j = 0; j < 4; j++) acc[i][j] = make_float2(0.f, 0.f);

    for (int k0 = 0; k0 < 64; k0 += 16) {
#pragma unroll
        for (int r = 0; r < 2; r++) {
            int row = lrow + r * 64;
            float4 a4 = *(const float4*)&A[(size_t)(m0 + row) * 512 + k0 + lf * 4];
            As[lf * 4 + 0][row] = a4.x; As[lf * 4 + 1][row] = a4.y;
            As[lf * 4 + 2][row] = a4.z; As[lf * 4 + 3][row] = a4.w;
        }
        {
            float4 b4 = *(const float4*)&Bm[(size_t)(n0 + lrow) * 512 + k0 + lf * 4];
            Bs[lf * 4 + 0][lrow] = b4.x; Bs[lf * 4 + 1][lrow] = b4.y;
            Bs[lf * 4 + 2][lrow] = b4.z; Bs[lf * 4 + 3][lrow] = b4.w;
        }
        __syncthreads();
#pragma unroll
        for (int kk = 0; kk < 16; kk++) {
            float4 a0 = *(const float4*)&As[kk][ty * 8];
            float4 a1 = *(const float4*)&As[kk][ty * 8 + 4];
            float4 b4 = *(const float4*)&Bs[kk][tx * 4];
            float2 a2[4] = { make_float2(a0.x, a0.y), make_float2(a0.z, a0.w),
                             make_float2(a1.x, a1.y), make_float2(a1.z, a1.w) };
            float bj[4] = { b4.x, b4.y, b4.z, b4.w };
#pragma unroll
            for (int j = 0; j < 4; j++) {
                float2 bd = fdup(bj[j]);
#pragma unroll
                for (int i = 0; i < 4; i++) ffma2(acc[i][j], a2[i], bd);
            }
        }
        __syncthreads();
    }

#pragma unroll
    for (int i = 0; i < 4; i++) {
        int m = m0 + ty * 8 + 2 * i;
        *(float4*)&C[(size_t)m * 512 + n0 + tx * 4] =
            make_float4(acc[i][0].x, acc[i][1].x, acc[i][2].x, acc[i][3].x);
        *(float4*)&C[(size_t)(m + 1) * 512 + n0 + tx * 4] =
            make_float4(acc[i][0].y, acc[i][1].y, acc[i][2].y, acc[i][3].y);
    }
}

// =============================================================================
// K3: fused per-(b,q). rels tile XOR-swizzled in smem, cp.async pipelined load
// overlapped with rel-score compute; softmax; probs@rels.
// smem: rels 512x64 fp32 (swizzled, 128KB), sc_s[8][516], q_s[512]
// =============================================================================
#define SMEM_FUSED ((512 * 64 + 8 * 516 + 512) * 4)

__global__ __launch_bounds__(256) void k_fused(
    const float* __restrict__ rels,
    const float* __restrict__ heads,
    float* __restrict__ out)
{
    extern __shared__ float sm[];
    float4* rv  = (float4*)sm;          // 512 rows x 16 float4 (swizzled)
    float* sc_s = sm + 512 * 64;        // 8 * 516
    float* q_s  = sc_s + 8 * 516;       // 512 (q transposed; later reduce buf)

    const int bq = blockIdx.x;
    const int b = bq >> 9, q = bq & 511;
    const int tid = threadIdx.x;
    const int lane = tid & 31, w = tid >> 5;

    const float* rg = rels + (size_t)bq * (512 * 64);

    // q load (global, lands while cp.asyncs issue)
    float4 qv;
    if (tid < 128)
        qv = *(const float4*)&g_q[((size_t)b * L_ + q) * HID_ + tid * 4];

    // ---- issue 8 cp.async groups: group g = rels rows [64g, 64g+64) ----
#pragma unroll
    for (int g = 0; g < 8; g++) {
#pragma unroll
        for (int i = 0; i < 4; i++) {
            int flat = g * 1024 + i * 256 + tid;   // float4 index
            int row = flat >> 4, d4 = flat & 15;
            cp_async16(&rv[row * 16 + (d4 ^ (row & 15))], rg + (size_t)flat * 4);
        }
        cp_commit();
    }

    if (tid < 128) {
        int e = tid * 4;
        q_s[((e + 0) & 63) * 8 + ((e + 0) >> 6)] = qv.x;
        q_s[((e + 1) & 63) * 8 + ((e + 1) >> 6)] = qv.y;
        q_s[((e + 2) & 63) * 8 + ((e + 2) >> 6)] = qv.z;
        q_s[((e + 3) & 63) * 8 + ((e + 3) >> 6)] = qv.w;
    }

    // ---- stage B per group: thread -> (k = g*64 + tid>>2, head pair tid&3)
    const int kl = tid >> 2;
    const int p  = tid & 3;
    const size_t hoff   = ((size_t)b * 512 + q) * 512;
    const size_t scoff0 = (((size_t)(b * 8 + 2 * p)) * 512 + q) * 512;
    const size_t scoff1 = scoff0 + (size_t)512 * 512;

#define GROUP_BODY(G, NWAIT)                                                   \
    do {                                                                       \
        cp_wait<NWAIT>();                                                      \
        __syncthreads();                                                       \
        const int k = (G) * 64 + kl;                                           \
        float2 acc = make_float2(0.f, 0.f);                                    \
        _Pragma("unroll")                                                      \
        for (int d4 = 0; d4 < 16; d4++) {                                      \
            float4 r4 = rv[k * 16 + (d4 ^ (k & 15))];                          \
            ffma2(acc, fdup(r4.x), *(const float2*)&q_s[(d4 * 4 + 0) * 8 + 2 * p]); \
            ffma2(acc, fdup(r4.y), *(const float2*)&q_s[(d4 * 4 + 1) * 8 + 2 * p]); \
            ffma2(acc, fdup(r4.z), *(const float2*)&q_s[(d4 * 4 + 2) * 8 + 2 * p]); \
            ffma2(acc, fdup(r4.w), *(const float2*)&q_s[(d4 * 4 + 3) * 8 + 2 * p]); \
        }                                                                      \
        float hv = heads[hoff + k];                                            \
        float s0 = g_sc[scoff0 + k];                                           \
        float s1 = g_sc[scoff1 + k];                                           \
        sc_s[(2 * p) * 516 + k]     = (acc.x + s0) * 0.125f + hv;              \
        sc_s[(2 * p + 1) * 516 + k] = (acc.y + s1) * 0.125f + hv;              \
    } while (0)

    GROUP_BODY(0, 7); GROUP_BODY(1, 6); GROUP_BODY(2, 5); GROUP_BODY(3, 4);
    GROUP_BODY(4, 3); GROUP_BODY(5, 2); GROUP_BODY(6, 1); GROUP_BODY(7, 0);
#undef GROUP_BODY
    __syncthreads();

    // ---- stage C: softmax, warp w == head w ----
    {
        float* row = sc_s + w * 516;
        float vals[16];
        float mx = -1e30f;
#pragma unroll
        for (int i = 0; i < 16; i++) { vals[i] = row[i * 32 + lane]; mx = fmaxf(mx, vals[i]); }
#pragma unroll
        for (int o = 16; o; o >>= 1) mx = fmaxf(mx, __shfl_xor_sync(0xffffffffu, mx, o));
        float s = 0.f;
#pragma unroll
        for (int i = 0; i < 16; i++) { vals[i] = __expf(vals[i] - mx); s += vals[i]; }
#pragma unroll
        for (int o = 16; o; o >>= 1) s += __shfl_xor_sync(0xffffffffu, s, o);
        float inv = 1.f / s;
        float* pg = g_sc + (((size_t)(b * 8 + w)) * 512 + q) * 512;
#pragma unroll
        for (int i = 0; i < 16; i++) {
            float pv = vals[i] * inv;
            row[i * 32 + lane] = pv;
            pg[i * 32 + lane] = pv;
        }
    }
    __syncthreads();

    // ---- stage D: rel-ctx = probs . rels (k-split by 2) ----
    {
        const int ks = tid >> 7;
        const int r  = tid & 127;
        const int h  = r >> 4;
        const int dq = r & 15;          // float4 column
        float2 c0 = make_float2(0.f, 0.f), c1 = make_float2(0.f, 0.f);
        const float* prow = sc_s + h * 516;
        const int kbeg = ks * 256;
#pragma unroll 8
        for (int k = kbeg; k < kbeg + 256; k += 4) {
            float4 p4 = *(const float4*)&prow[k];
            float pj[4] = { p4.x, p4.y, p4.z, p4.w };
#pragma unroll
            for (int j = 0; j < 4; j++) {
                float4 r4 = rv[(k + j) * 16 + (dq ^ ((k + j) & 15))];
                float2 pd = fdup(pj[j]);
                ffma2(c0, pd, make_float2(r4.x, r4.y));
                ffma2(c1, pd, make_float2(r4.z, r4.w));
            }
        }
        if (ks == 1) {
            *(float4*)&q_s[r * 4] = make_float4(c0.x, c0.y, c1.x, c1.y);
        }
        __syncthreads();
        if (ks == 0) {
            float4 t = *(const float4*)&q_s[r * 4];
            float4 o = make_float4(c0.x + t.x, c0.y + t.y, c1.x + t.z, c1.y + t.w);
            *(float4*)&out[(size_t)bq * 512 + h * 64 + dq * 4] = o;
        }
    }
}

// =============================================================================
// K4: ctx += probs @ v per (b,h).  BM=64(q), BN=64(d), K=512.
// grid (8, 32) = 256 CTAs, 2 CTAs/SM.
// =============================================================================
__global__ __launch_bounds__(256) void k_ctx(float* __restrict__ out)
{
    __shared__ float As[16][68];    // probs^T: [kk][m]
    __shared__ float Bs[16][68];    // v: [kk][n]

    const int bh = blockIdx.y;
    const int b = bh >> 3, h = bh & 7;
    const int m0 = blockIdx.x * 64;
    const float* P = g_sc + (size_t)bh * L_ * L_;
    const float* V = g_v + (size_t)b * L_ * HID_ + h * DH_;

    const int tid = threadIdx.x;
    const int tx = tid & 15, ty = tid >> 4;   // cols tx*4, rows ty*4
    const int lrow = tid >> 2;
    const int lf   = tid & 3;
    const int vrow = tid >> 4;
    const int vc   = tid & 15;

    float2 acc[2][4];
#pragma unroll
    for (int i = 0; i < 2; i++)
#pragma unroll
        for (int j = 0; j < 4; j++) acc[i][j] = make_float2(0.f, 0.f);

    for (int k0 = 0; k0 < 512; k0 += 16) {
        {
            float4 a4 = *(const float4*)&P[(size_t)(m0 + lrow) * 512 + k0 + lf * 4];
            As[lf * 4 + 0][lrow] = a4.x; As[lf * 4 + 1][lrow] = a4.y;
            As[lf * 4 + 2][lrow] = a4.z; As[lf * 4 + 3][lrow] = a4.w;
        }
        {
            float4 b4 = *(const float4*)&V[(size_t)(k0 + vrow) * 512 + vc * 4];
            *(float4*)&Bs[vrow][vc * 4] = b4;
        }
        __syncthreads();
#pragma unroll
        for (int kk = 0; kk < 16; kk++) {
            float4 a4 = *(const float4*)&As[kk][ty * 4];
            float4 b4 = *(const float4*)&Bs[kk][tx * 4];
            float2 a2[2] = { make_float2(a4.x, a4.y), make_float2(a4.z, a4.w) };
            float bj[4] = { b4.x, b4.y, b4.z, b4.w };
#pragma unroll
            for (int j = 0; j < 4; j++) {
                float2 bd = fdup(bj[j]);
#pragma unroll
                for (int i = 0; i < 2; i++) ffma2(acc[i][j], a2[i], bd);
            }
        }
        __syncthreads();
    }

#pragma unroll
    for (int i = 0; i < 2; i++) {
        int m = m0 + ty * 4 + 2 * i;
        float4* p0 = (float4*)&out[((size_t)b * 512 + m) * 512 + h * 64 + tx * 4];
        float4 c0 = *p0;
        c0.x += acc[i][0].x; c0.y += acc[i][1].x; c0.z += acc[i][2].x; c0.w += acc[i][3].x;
        *p0 = c0;
        float4* p1 = (float4*)&out[((size_t)b * 512 + m + 1) * 512 + h * 64 + tx * 4];
        float4 c1 = *p1;
        c1.x += acc[i][0].y; c1.y += acc[i][1].y; c1.z += acc[i][2].y; c1.w += acc[i][3].y;
        *p1 = c1;
    }
}

// =============================================================================
extern "C" void kernel_launch(void* const* d_in, const int* in_sizes, int n_in,
                              void* d_out, int out_size)
{
    const float* hidden = (const float*)d_in[0];
    const float* heads  = (const float*)d_in[1];
    const float* rels   = (const float*)d_in[2];
    const float* Wq = (const float*)d_in[3];
    const float* bq = (const float*)d_in[4];
    const float* Wk = (const float*)d_in[5];
    const float* bk = (const float*)d_in[6];
    const float* Wv = (const float*)d_in[7];
    const float* bv = (const float*)d_in[8];
    float* out = (float*)d_out;

    dim3 g1(8, 16, 3);
    k_proj<<<g1, 256>>>(hidden, Wq, bq, Wk, bk, Wv, bv);

    dim3 g2(8, 4, 32);
    k_scores<<<g2, 256>>>();

    cudaFuncSetAttribute(k_fused, cudaFuncAttributeMaxDynamicSharedMemorySize, SMEM_FUSED);
    k_fused<<<2048, 256, SMEM_FUSED>>>(rels, heads, out);

    dim3 g4(8, 32);
    k_ctx<<<g4, 256>>>(out);
}